// round 12
// baseline (speedup 1.0000x reference)
#include <cuda_runtime.h>
#include <cstdint>

// PANNAcceptor: out[b] = lin_w @ (W[x_{L-1}] ... W[x_0] e0) + lin_b
// Round 12: fp24 row-PAIR packing -- 3x LDG.128 per 2 rows (25% fewer L2
// requests than R11) + K=40 LPT workers (was 96: oversubscription starved
// the straggler).
//   Evidence: fp32 and fp24(R11) both pinned at ~29 steps/us chip-wide with
//   EQUAL warp-LDG counts (512/step) despite 25% different bytes -> the
//   chip cap tracks L2 requests, not bytes. This round cuts requests to
//   384/step with bytes unchanged.
//   Block layout per row pair (1536B): [hi r0 512B][hi r1 512B][lo 512B],
//   lo interleaved so lane l's uint4 at 1024+16l = {r0 cols[8l..8l+8) lo,
//   r1 cols[8l..8l+8) lo}. Decode = validated lattice PRMT (rel 1.7e-4).

#define NST  256
#define TPB  512          // 16 warps; each warp owns 8 row-pairs (16 rows)
#define MAXA 128
#define MAXB 1024
#define KCTA 40
#define PAIRB 1536        // bytes per packed row pair

__device__ unsigned char g_w24[(size_t)MAXA * (NST / 2) * PAIRB];  // 25.2MB
__device__ int g_order[MAXB];
__device__ int g_next;

// ---------------- quantize: fp32 -> packed pair-planar fp24 ----------------
// decoded bits = (H<<16) | (L<<8) | L = H*65536 + L*257 (nearest lattice pt)
__global__ void pann_quant(const float* __restrict__ W, int total4)
{
    for (int i = blockIdx.x * blockDim.x + threadIdx.x; i < total4;
         i += gridDim.x * blockDim.x) {
        const float4 f = ((const float4*)W)[i];
        uint32_t u0 = __float_as_uint(f.x), u1 = __float_as_uint(f.y);
        uint32_t u2 = __float_as_uint(f.z), u3 = __float_as_uint(f.w);
        uint32_t l0 = ((u0 & 0xFFFFu) * 255u + 32768u) >> 16;
        uint32_t l1 = ((u1 & 0xFFFFu) * 255u + 32768u) >> 16;
        uint32_t l2 = ((u2 & 0xFFFFu) * 255u + 32768u) >> 16;
        uint32_t l3 = ((u3 & 0xFFFFu) * 255u + 32768u) >> 16;
        ushort4 h;
        h.x = (unsigned short)(u0 >> 16);
        h.y = (unsigned short)(u1 >> 16);
        h.z = (unsigned short)(u2 >> 16);
        h.w = (unsigned short)(u3 >> 16);

        const int col4   = i & 63;          // float4 index within row (64/row)
        const int row    = i >> 6;          // global row (a*256 + r)
        const int pair   = row >> 1;
        const int parity = row & 1;
        unsigned char* pb = g_w24 + (size_t)pair * PAIRB;

        // hi plane: parity selects 512B half; col c at byte 2c
        *(ushort4*)(pb + parity * 512 + col4 * 8) = h;

        // lo plane (interleaved): group g = 8-col group, half = which 4 cols
        const int g    = col4 >> 1;
        const int half = col4 & 1;
        *(uint32_t*)(pb + 1024 + g * 16 + parity * 8 + half * 4) =
            l0 | (l1 << 8) | (l2 << 16) | (l3 << 24);
    }
}

// ---------------- scheduler: rank batches by (L desc, idx) ----------------
__global__ void pann_sched(const int* __restrict__ lengths, int B)
{
    const int tid = threadIdx.x;
    if (tid == 0) g_next = 0;
    if (tid < B) {
        const int L = lengths[tid];
        int rank = 0;
        for (int s = 0; s < B; ++s) {
            const int L2 = lengths[s];
            rank += (L2 > L) || (L2 == L && s < tid);
        }
        g_order[rank] = tid;
    }
}

__device__ __forceinline__ float pf(uint32_t hw, uint32_t lw, uint32_t sel) {
    return __uint_as_float(__byte_perm(hw, lw, sel));
}
__device__ __forceinline__ float warp_reduce16(float v) {
    v += __shfl_xor_sync(0xffffffffu, v, 8);
    v += __shfl_xor_sync(0xffffffffu, v, 4);
    v += __shfl_xor_sync(0xffffffffu, v, 2);
    v += __shfl_xor_sync(0xffffffffu, v, 1);
    return v;
}

// decode 8 cols of one row from its hi uint4 + two lo words
__device__ __forceinline__ float dot8(const uint4 H, uint32_t Ll, uint32_t Lh,
                                      const float4 h0, const float4 h1)
{
    const float e0 = pf(H.x, Ll, 0x1044u);
    const float e1 = pf(H.x, Ll, 0x3255u);
    const float e2 = pf(H.y, Ll, 0x1066u);
    const float e3 = pf(H.y, Ll, 0x3277u);
    const float e4 = pf(H.z, Lh, 0x1044u);
    const float e5 = pf(H.z, Lh, 0x3255u);
    const float e6 = pf(H.w, Lh, 0x1066u);
    const float e7 = pf(H.w, Lh, 0x3277u);
    return e0*h0.x + e1*h0.y + e2*h0.z + e3*h0.w
         + e4*h1.x + e5*h1.y + e6*h1.z + e7*h1.w;
}

// ---------------- persistent LPT worker (fp24 pairs) ----------------
__global__ __launch_bounds__(TPB, 1)
void pann_lpt24p(const int* __restrict__ xs,
                 const int* __restrict__ lengths,
                 const float* __restrict__ lin_w,
                 const float* __restrict__ lin_b,
                 float* __restrict__ out,
                 int S, int B)
{
    __shared__ float hbuf[2][NST];
    __shared__ int s_b;

    const int tid  = threadIdx.x;
    const int warp = tid >> 5;
    const int lane = tid & 31;
    const int i0 = warp * 16;            // this warp's 16 rows (8 pairs)

    for (;;) {
        if (tid == 0) {
            const int idx = atomicAdd(&g_next, 1);
            s_b = (idx < B) ? g_order[idx] : -1;
        }
        __syncthreads();
        const int b = s_b;
        if (b < 0) return;

        if (tid < NST) hbuf[0][tid] = (tid == 0) ? 1.0f : 0.0f;

        const int L = lengths[b];
        const int* xrow = xs + (size_t)b * S;
        __syncthreads();

        int cur = 0;
        int a = __ldg(xrow);

        for (int t = 0; t < L; ++t) {
            const int a_cur = a;
            if (t + 1 < L) a = __ldg(xrow + t + 1);   // prefetch next symbol

            // base of this warp's 8 row-pair blocks; per-pair offsets are
            // compile-time immediates (p*1536 + {0,512,1024}) from one base.
            const unsigned char* basep =
                g_w24 + (size_t)(a_cur * (NST / 2) + (i0 >> 1)) * PAIRB
                + lane * 16;

            const float* hsrc = hbuf[cur];
            float* hdst = hbuf[cur ^ 1];

            // lane's h slice: cols [8l, 8l+8)
            const float4 h0 = ((const float4*)hsrc)[2 * lane];
            const float4 h1 = ((const float4*)hsrc)[2 * lane + 1];

            #pragma unroll 4
            for (int p = 0; p < 8; ++p) {
                const uint4 H0 = *(const uint4*)(basep + p * PAIRB);
                const uint4 H1 = *(const uint4*)(basep + p * PAIRB + 512);
                const uint4 Lp = *(const uint4*)(basep + p * PAIRB + 1024);

                float sA = dot8(H0, Lp.x, Lp.y, h0, h1);   // row 2p
                float sB = dot8(H1, Lp.z, Lp.w, h0, h1);   // row 2p+1

                // fold: lanes<16 reduce row 2p, lanes>=16 reduce row 2p+1
                const float oA = __shfl_xor_sync(0xffffffffu, sA, 16);
                const float oB = __shfl_xor_sync(0xffffffffu, sB, 16);
                float v = (lane < 16) ? (sA + oA) : (sB + oB);
                v = warp_reduce16(v);
                const int i = i0 + 2 * p;
                if (lane == 0)  hdst[i]     = v;
                if (lane == 16) hdst[i + 1] = v;
            }
            __syncthreads();
            cur ^= 1;
        }

        // ---- linear head ----
        const float* hf = hbuf[L & 1];
        if (warp < 2) {
            float s = 0.0f;
            #pragma unroll
            for (int i = lane; i < NST; i += 32)
                s += lin_w[warp * NST + i] * hf[i];
            s += __shfl_xor_sync(0xffffffffu, s, 16);
            s = warp_reduce16(s);
            if (lane == 0) out[b * 2 + warp] = s + lin_b[warp];
        }
    }
}

// ---------------- fallback (plain R1) for unexpected shapes ----------------
__global__ __launch_bounds__(512, 1)
void pann_chain_fp32(const int* __restrict__ xs,
                     const int* __restrict__ lengths,
                     const float* __restrict__ W,
                     const float* __restrict__ lin_w,
                     const float* __restrict__ lin_b,
                     float* __restrict__ out,
                     int S)
{
    __shared__ float hbuf[2][NST];
    const int b = blockIdx.x, tid = threadIdx.x, warp = tid >> 5, lane = tid & 31;
    if (tid < NST) hbuf[0][tid] = (tid == 0) ? 1.0f : 0.0f;
    const int L = lengths[b];
    const int* xrow = xs + (size_t)b * S;
    __syncthreads();
    int cur = 0;
    const int i0 = warp * 16;
    for (int t = 0; t < L; ++t) {
        const int a = __ldg(xrow + t);
        const float* Wa = W + (size_t)a * (NST * NST);
        const float* hsrc = hbuf[cur];
        float* hdst = hbuf[cur ^ 1];
        const float4 hA = ((const float4*)hsrc)[lane];
        const float4 hB = ((const float4*)hsrc)[32 + lane];
        #pragma unroll 4
        for (int r = 0; r < 16; ++r) {
            const int i = i0 + r;
            const float4* p = (const float4*)(Wa + (size_t)i * NST + lane * 4);
            const float4 wA = p[0];
            const float4 wB = p[32];
            float s = wA.x*hA.x + wA.y*hA.y + wA.z*hA.z + wA.w*hA.w
                    + wB.x*hB.x + wB.y*hB.y + wB.z*hB.z + wB.w*hB.w;
            s += __shfl_xor_sync(0xffffffffu, s, 16);
            s = warp_reduce16(s);
            if (lane == 0) hdst[i] = s;
        }
        __syncthreads();
        cur ^= 1;
    }
    const float* hf = hbuf[cur];
    if (warp < 2) {
        float s = 0.0f;
        #pragma unroll
        for (int i = lane; i < NST; i += 32) s += lin_w[warp * NST + i] * hf[i];
        s += __shfl_xor_sync(0xffffffffu, s, 16);
        s = warp_reduce16(s);
        if (lane == 0) out[b * 2 + warp] = s + lin_b[warp];
    }
}

extern "C" void kernel_launch(void* const* d_in, const int* in_sizes, int n_in,
                              void* d_out, int out_size)
{
    const int*   xs      = (const int*)d_in[0];
    const int*   lengths = (const int*)d_in[1];
    const float* W       = (const float*)d_in[2];
    const float* lin_w   = (const float*)d_in[3];
    const float* lin_b   = (const float*)d_in[4];
    float*       out     = (float*)d_out;

    const int B = in_sizes[1];
    const int S = in_sizes[0] / B;
    const int A = in_sizes[2] / (NST * NST);

    if (A >= 1 && A <= MAXA && B >= 1 && B <= MAXB) {
        const int total4 = in_sizes[2] / 4;
        pann_quant<<<2048, 256>>>(W, total4);
        const int sthreads = ((B + 31) / 32 * 32) < 32 ? 32 : ((B + 31) / 32 * 32);
        pann_sched<<<1, sthreads>>>(lengths, B);
        const int K = (B < KCTA) ? B : KCTA;
        pann_lpt24p<<<K, TPB>>>(xs, lengths, lin_w, lin_b, out, S, B);
    } else {
        pann_chain_fp32<<<B, 512>>>(xs, lengths, W, lin_w, lin_b, out, S);
    }
}

// round 13
// speedup vs baseline: 2.2645x; 2.2645x over previous
#include <cuda_runtime.h>
#include <cstdint>

// PANNAcceptor: out[b] = lin_w @ (W[x_{L-1}] ... W[x_0] e0) + lin_b
// Round 13: mixed-precision LPT.
//   Measured: chip LTS byte cap ~7.5 TB/s; fp32 streaming is byte-bound
//   (2.29ms); fp24 cuts bytes 25% but its decode halves per-CTA solo rate,
//   making the LONGEST chain the binding constraint (R11 = 2210us).
//   Fix: the 8 longest chains (LPT ranks 0..7) run the proven fully-
//   pipelined fp32 loop (solo ~0.93 steps/us); everything else runs the
//   fp24 loop (75% of the bytes). Bulk floor ~13.1GB/7.5TB/s = 1.75ms,
//   straggler ~1.8-1.9ms -> both constraints relieved simultaneously.

#define NST  256
#define TPB  512          // 16 warps, 16 rows each
#define MAXA 128
#define MAXB 1024
#define KCTA 64
#define ROWB 768          // fp24 packed row: 512B hi(u16) + 256B lo(u8)
#define FP32_TOP 8        // this many longest chains use the fp32 path

__device__ unsigned char g_w24[(size_t)MAXA * NST * ROWB];
__device__ int g_order[MAXB];
__device__ int g_next;

// ---------------- quantize: fp32 -> packed planar fp24 (R11 layout) --------
// decoded bits = (H<<16) | (L<<8) | L = H*65536 + L*257 (nearest lattice pt)
__global__ void pann_quant(const float* __restrict__ W, int total4)
{
    for (int i = blockIdx.x * blockDim.x + threadIdx.x; i < total4;
         i += gridDim.x * blockDim.x) {
        const float4 f = ((const float4*)W)[i];
        uint32_t u0 = __float_as_uint(f.x), u1 = __float_as_uint(f.y);
        uint32_t u2 = __float_as_uint(f.z), u3 = __float_as_uint(f.w);
        uint32_t l0 = ((u0 & 0xFFFFu) * 255u + 32768u) >> 16;
        uint32_t l1 = ((u1 & 0xFFFFu) * 255u + 32768u) >> 16;
        uint32_t l2 = ((u2 & 0xFFFFu) * 255u + 32768u) >> 16;
        uint32_t l3 = ((u3 & 0xFFFFu) * 255u + 32768u) >> 16;
        ushort4 h;
        h.x = (unsigned short)(u0 >> 16);
        h.y = (unsigned short)(u1 >> 16);
        h.z = (unsigned short)(u2 >> 16);
        h.w = (unsigned short)(u3 >> 16);

        const int col4 = i & 63;            // 64 float4 per row
        const int row  = i >> 6;            // global row (a*256 + r)
        unsigned char* rb = g_w24 + (size_t)row * ROWB;
        *(ushort4*)(rb + col4 * 8) = h;                        // hi plane
        *(uint32_t*)(rb + 512 + col4 * 4) =
            l0 | (l1 << 8) | (l2 << 16) | (l3 << 24);          // lo plane
    }
}

// ---------------- scheduler: rank batches by (L desc, idx) ----------------
__global__ void pann_sched(const int* __restrict__ lengths, int B)
{
    const int tid = threadIdx.x;
    if (tid == 0) g_next = 0;
    if (tid < B) {
        const int L = lengths[tid];
        int rank = 0;
        for (int s = 0; s < B; ++s) {
            const int L2 = lengths[s];
            rank += (L2 > L) || (L2 == L && s < tid);
        }
        g_order[rank] = tid;
    }
}

__device__ __forceinline__ float pf(uint32_t hw, uint32_t lw, uint32_t sel) {
    return __uint_as_float(__byte_perm(hw, lw, sel));
}
__device__ __forceinline__ float warp_reduce16(float v) {
    v += __shfl_xor_sync(0xffffffffu, v, 8);
    v += __shfl_xor_sync(0xffffffffu, v, 4);
    v += __shfl_xor_sync(0xffffffffu, v, 2);
    v += __shfl_xor_sync(0xffffffffu, v, 1);
    return v;
}

// ---------------- persistent mixed-precision LPT worker ----------------
__global__ __launch_bounds__(TPB, 1)
void pann_mix(const int* __restrict__ xs,
              const int* __restrict__ lengths,
              const float* __restrict__ W,
              const float* __restrict__ lin_w,
              const float* __restrict__ lin_b,
              float* __restrict__ out,
              int S, int B)
{
    __shared__ float hbuf[2][NST];
    __shared__ int s_b, s_fp32;

    const int tid  = threadIdx.x;
    const int warp = tid >> 5;
    const int lane = tid & 31;
    const int i0 = warp * 16;            // this warp's 16 rows

    for (;;) {
        if (tid == 0) {
            const int idx = atomicAdd(&g_next, 1);
            s_b    = (idx < B) ? g_order[idx] : -1;
            s_fp32 = (idx < FP32_TOP);
        }
        __syncthreads();
        const int b = s_b;
        if (b < 0) return;
        const bool use32 = s_fp32;

        if (tid < NST) hbuf[0][tid] = (tid == 0) ? 1.0f : 0.0f;

        const int L = lengths[b];
        const int* xrow = xs + (size_t)b * S;
        __syncthreads();

        int cur = 0;
        int a = __ldg(xrow);

        if (use32) {
            // ======== fp32 path (exact R10 loop; fully pipelined) ========
            for (int t = 0; t < L; ++t) {
                const int a_cur = a;
                if (t + 1 < L) a = __ldg(xrow + t + 1);

                const float* Wa = W + (size_t)a_cur * (NST * NST);
                const float* hsrc = hbuf[cur];
                float* hdst = hbuf[cur ^ 1];

                const float4 hA = ((const float4*)hsrc)[lane];
                const float4 hB = ((const float4*)hsrc)[32 + lane];

                #pragma unroll 4
                for (int r = 0; r < 16; ++r) {
                    const int i = i0 + r;
                    const float4* p = (const float4*)(Wa + (size_t)i * NST + lane * 4);
                    const float4 wA = p[0];
                    const float4 wB = p[32];
                    float s = wA.x*hA.x + wA.y*hA.y + wA.z*hA.z + wA.w*hA.w
                            + wB.x*hB.x + wB.y*hB.y + wB.z*hB.z + wB.w*hB.w;
                    s += __shfl_xor_sync(0xffffffffu, s, 16);
                    s = warp_reduce16(s);
                    if (lane == 0) hdst[i] = s;
                }
                __syncthreads();
                cur ^= 1;
            }
        } else {
            // ======== fp24 path (exact R11 loop) ========
            for (int t = 0; t < L; ++t) {
                const int a_cur = a;
                if (t + 1 < L) a = __ldg(xrow + t + 1);

                const unsigned char* basew =
                    g_w24 + (size_t)(a_cur * NST + i0) * ROWB;
                const unsigned char* ph = basew + lane * 16;       // hi slice
                const unsigned char* pl = basew + 512 + lane * 8;  // lo slice

                const float* hsrc = hbuf[cur];
                float* hdst = hbuf[cur ^ 1];

                const float4 h0 = ((const float4*)hsrc)[2 * lane];
                const float4 h1 = ((const float4*)hsrc)[2 * lane + 1];

                #pragma unroll 4
                for (int r = 0; r < 16; ++r) {
                    const uint4 H  = *(const uint4*)(ph + r * ROWB);
                    const uint2 Lw = *(const uint2*)(pl + r * ROWB);

                    const float e0 = pf(H.x, Lw.x, 0x1044u);
                    const float e1 = pf(H.x, Lw.x, 0x3255u);
                    const float e2 = pf(H.y, Lw.x, 0x1066u);
                    const float e3 = pf(H.y, Lw.x, 0x3277u);
                    const float e4 = pf(H.z, Lw.y, 0x1044u);
                    const float e5 = pf(H.z, Lw.y, 0x3255u);
                    const float e6 = pf(H.w, Lw.y, 0x1066u);
                    const float e7 = pf(H.w, Lw.y, 0x3277u);

                    float s = e0*h0.x + e1*h0.y + e2*h0.z + e3*h0.w
                            + e4*h1.x + e5*h1.y + e6*h1.z + e7*h1.w;

                    s += __shfl_xor_sync(0xffffffffu, s, 16);
                    s = warp_reduce16(s);
                    if (lane == 0) hdst[i0 + r] = s;
                }
                __syncthreads();
                cur ^= 1;
            }
        }

        // ---- linear head ----
        const float* hf = hbuf[L & 1];
        if (warp < 2) {
            float s = 0.0f;
            #pragma unroll
            for (int i = lane; i < NST; i += 32)
                s += lin_w[warp * NST + i] * hf[i];
            s += __shfl_xor_sync(0xffffffffu, s, 16);
            s = warp_reduce16(s);
            if (lane == 0) out[b * 2 + warp] = s + lin_b[warp];
        }
    }
}

// ---------------- fallback (plain R1) for unexpected shapes ----------------
__global__ __launch_bounds__(512, 1)
void pann_chain_fp32(const int* __restrict__ xs,
                     const int* __restrict__ lengths,
                     const float* __restrict__ W,
                     const float* __restrict__ lin_w,
                     const float* __restrict__ lin_b,
                     float* __restrict__ out,
                     int S)
{
    __shared__ float hbuf[2][NST];
    const int b = blockIdx.x, tid = threadIdx.x, warp = tid >> 5, lane = tid & 31;
    if (tid < NST) hbuf[0][tid] = (tid == 0) ? 1.0f : 0.0f;
    const int L = lengths[b];
    const int* xrow = xs + (size_t)b * S;
    __syncthreads();
    int cur = 0;
    const int i0 = warp * 16;
    for (int t = 0; t < L; ++t) {
        const int a = __ldg(xrow + t);
        const float* Wa = W + (size_t)a * (NST * NST);
        const float* hsrc = hbuf[cur];
        float* hdst = hbuf[cur ^ 1];
        const float4 hA = ((const float4*)hsrc)[lane];
        const float4 hB = ((const float4*)hsrc)[32 + lane];
        #pragma unroll 4
        for (int r = 0; r < 16; ++r) {
            const int i = i0 + r;
            const float4* p = (const float4*)(Wa + (size_t)i * NST + lane * 4);
            const float4 wA = p[0];
            const float4 wB = p[32];
            float s = wA.x*hA.x + wA.y*hA.y + wA.z*hA.z + wA.w*hA.w
                    + wB.x*hB.x + wB.y*hB.y + wB.z*hB.z + wB.w*hB.w;
            s += __shfl_xor_sync(0xffffffffu, s, 16);
            s = warp_reduce16(s);
            if (lane == 0) hdst[i] = s;
        }
        __syncthreads();
        cur ^= 1;
    }
    const float* hf = hbuf[cur];
    if (warp < 2) {
        float s = 0.0f;
        #pragma unroll
        for (int i = lane; i < NST; i += 32) s += lin_w[warp * NST + i] * hf[i];
        s += __shfl_xor_sync(0xffffffffu, s, 16);
        s = warp_reduce16(s);
        if (lane == 0) out[b * 2 + warp] = s + lin_b[warp];
    }
}

extern "C" void kernel_launch(void* const* d_in, const int* in_sizes, int n_in,
                              void* d_out, int out_size)
{
    const int*   xs      = (const int*)d_in[0];
    const int*   lengths = (const int*)d_in[1];
    const float* W       = (const float*)d_in[2];
    const float* lin_w   = (const float*)d_in[3];
    const float* lin_b   = (const float*)d_in[4];
    float*       out     = (float*)d_out;

    const int B = in_sizes[1];
    const int S = in_sizes[0] / B;
    const int A = in_sizes[2] / (NST * NST);

    if (A >= 1 && A <= MAXA && B >= 1 && B <= MAXB) {
        const int total4 = in_sizes[2] / 4;
        pann_quant<<<2048, 256>>>(W, total4);
        const int sthreads = ((B + 31) / 32 * 32) < 32 ? 32 : ((B + 31) / 32 * 32);
        pann_sched<<<1, sthreads>>>(lengths, B);
        const int K = (B < KCTA) ? B : KCTA;
        pann_mix<<<K, TPB>>>(xs, lengths, W, lin_w, lin_b, out, S, B);
    } else {
        pann_chain_fp32<<<B, 512>>>(xs, lengths, W, lin_w, lin_b, out, S);
    }
}

// round 14
// speedup vs baseline: 2.3271x; 1.0276x over previous
#include <cuda_runtime.h>
#include <cstdint>

// PANNAcceptor: out[b] = lin_w @ (W[x_{L-1}] ... W[x_0] e0) + lin_b
// Round 14: R11 (fp24 packed rows + LPT persistent workers) with K=128.
//   Model: for fp24 the chip is DEMAND-limited (per-CTA rate ~0.31 steps/us
//   is latency-bound by the decode between loads), not cap-limited; R11 ran
//   96 CTAs = 29.7 steps/us while the fp24 line/byte cap allows ~38.
//   K=128 (1 CTA/SM on 128 of 148 SMs) raises demand to ~40 steps/us,
//   reaching the cap -> predicted ~1.8ms. Single-knob change vs R11.
//   fp24 lattice decode validated at rel_err 1.712e-4 (gate 1e-3).

#define NST  256
#define TPB  512          // 16 warps, 16 rows each
#define MAXA 128
#define MAXB 1024
#define KCTA 128
#define ROWB 768          // packed row: 512B hi(u16) + 256B lo(u8)

__device__ unsigned char g_w24[(size_t)MAXA * NST * ROWB];   // 25.2 MB @128
__device__ int g_order[MAXB];
__device__ int g_next;

// ---------------- quantize: fp32 -> packed planar fp24 ----------------
// decoded bits = (H<<16) | (L<<8) | L = H*65536 + L*257 (nearest lattice pt)
__global__ void pann_quant(const float* __restrict__ W, int total4)
{
    for (int i = blockIdx.x * blockDim.x + threadIdx.x; i < total4;
         i += gridDim.x * blockDim.x) {
        const float4 f = ((const float4*)W)[i];
        uint32_t u0 = __float_as_uint(f.x), u1 = __float_as_uint(f.y);
        uint32_t u2 = __float_as_uint(f.z), u3 = __float_as_uint(f.w);
        uint32_t l0 = ((u0 & 0xFFFFu) * 255u + 32768u) >> 16;
        uint32_t l1 = ((u1 & 0xFFFFu) * 255u + 32768u) >> 16;
        uint32_t l2 = ((u2 & 0xFFFFu) * 255u + 32768u) >> 16;
        uint32_t l3 = ((u3 & 0xFFFFu) * 255u + 32768u) >> 16;
        ushort4 h;
        h.x = (unsigned short)(u0 >> 16);
        h.y = (unsigned short)(u1 >> 16);
        h.z = (unsigned short)(u2 >> 16);
        h.w = (unsigned short)(u3 >> 16);

        const int col4 = i & 63;            // 64 float4 per row
        const int row  = i >> 6;            // global row (a*256 + r)
        unsigned char* rb = g_w24 + (size_t)row * ROWB;
        *(ushort4*)(rb + col4 * 8) = h;                        // hi plane
        *(uint32_t*)(rb + 512 + col4 * 4) =
            l0 | (l1 << 8) | (l2 << 16) | (l3 << 24);          // lo plane
    }
}

// ---------------- scheduler: rank batches by (L desc, idx) ----------------
__global__ void pann_sched(const int* __restrict__ lengths, int B)
{
    const int tid = threadIdx.x;
    if (tid == 0) g_next = 0;
    if (tid < B) {
        const int L = lengths[tid];
        int rank = 0;
        for (int s = 0; s < B; ++s) {
            const int L2 = lengths[s];
            rank += (L2 > L) || (L2 == L && s < tid);
        }
        g_order[rank] = tid;
    }
}

__device__ __forceinline__ float pf(uint32_t hw, uint32_t lw, uint32_t sel) {
    return __uint_as_float(__byte_perm(hw, lw, sel));
}
__device__ __forceinline__ float warp_reduce16(float v) {
    v += __shfl_xor_sync(0xffffffffu, v, 8);
    v += __shfl_xor_sync(0xffffffffu, v, 4);
    v += __shfl_xor_sync(0xffffffffu, v, 2);
    v += __shfl_xor_sync(0xffffffffu, v, 1);
    return v;
}

// ---------------- persistent LPT worker (fp24) ----------------
__global__ __launch_bounds__(TPB, 1)
void pann_lpt24(const int* __restrict__ xs,
                const int* __restrict__ lengths,
                const float* __restrict__ lin_w,
                const float* __restrict__ lin_b,
                float* __restrict__ out,
                int S, int B)
{
    __shared__ float hbuf[2][NST];
    __shared__ int s_b;

    const int tid  = threadIdx.x;
    const int warp = tid >> 5;
    const int lane = tid & 31;
    const int i0 = warp * 16;            // this warp's 16 rows

    for (;;) {
        if (tid == 0) {
            const int idx = atomicAdd(&g_next, 1);
            s_b = (idx < B) ? g_order[idx] : -1;
        }
        __syncthreads();
        const int b = s_b;
        if (b < 0) return;

        if (tid < NST) hbuf[0][tid] = (tid == 0) ? 1.0f : 0.0f;

        const int L = lengths[b];
        const int* xrow = xs + (size_t)b * S;
        __syncthreads();

        int cur = 0;
        int a = __ldg(xrow);

        for (int t = 0; t < L; ++t) {
            const int a_cur = a;
            if (t + 1 < L) a = __ldg(xrow + t + 1);   // prefetch next symbol

            // two base pointers; per-row offsets are compile-time immediates
            // (r*768) so ptxas front-batches the loads (MLP ~8).
            const unsigned char* basew =
                g_w24 + (size_t)(a_cur * NST + i0) * ROWB;
            const unsigned char* ph = basew + lane * 16;         // hi slice
            const unsigned char* pl = basew + 512 + lane * 8;    // lo slice

            const float* hsrc = hbuf[cur];
            float* hdst = hbuf[cur ^ 1];

            // lane's h slice: cols [8l, 8l+8)
            const float4 h0 = ((const float4*)hsrc)[2 * lane];
            const float4 h1 = ((const float4*)hsrc)[2 * lane + 1];

            #pragma unroll 4
            for (int r = 0; r < 16; ++r) {
                const uint4 H  = *(const uint4*)(ph + r * ROWB);
                const uint2 Lw = *(const uint2*)(pl + r * ROWB);

                const float e0 = pf(H.x, Lw.x, 0x1044u);
                const float e1 = pf(H.x, Lw.x, 0x3255u);
                const float e2 = pf(H.y, Lw.x, 0x1066u);
                const float e3 = pf(H.y, Lw.x, 0x3277u);
                const float e4 = pf(H.z, Lw.y, 0x1044u);
                const float e5 = pf(H.z, Lw.y, 0x3255u);
                const float e6 = pf(H.w, Lw.y, 0x1066u);
                const float e7 = pf(H.w, Lw.y, 0x3277u);

                float s = e0*h0.x + e1*h0.y + e2*h0.z + e3*h0.w
                        + e4*h1.x + e5*h1.y + e6*h1.z + e7*h1.w;

                s += __shfl_xor_sync(0xffffffffu, s, 16);
                s = warp_reduce16(s);
                if (lane == 0) hdst[i0 + r] = s;
            }
            __syncthreads();
            cur ^= 1;
        }

        // ---- linear head ----
        const float* hf = hbuf[L & 1];
        if (warp < 2) {
            float s = 0.0f;
            #pragma unroll
            for (int i = lane; i < NST; i += 32)
                s += lin_w[warp * NST + i] * hf[i];
            s += __shfl_xor_sync(0xffffffffu, s, 16);
            s = warp_reduce16(s);
            if (lane == 0) out[b * 2 + warp] = s + lin_b[warp];
        }
    }
}

// ---------------- fallback (plain R1) for unexpected shapes ----------------
__global__ __launch_bounds__(512, 1)
void pann_chain_fp32(const int* __restrict__ xs,
                     const int* __restrict__ lengths,
                     const float* __restrict__ W,
                     const float* __restrict__ lin_w,
                     const float* __restrict__ lin_b,
                     float* __restrict__ out,
                     int S)
{
    __shared__ float hbuf[2][NST];
    const int b = blockIdx.x, tid = threadIdx.x, warp = tid >> 5, lane = tid & 31;
    if (tid < NST) hbuf[0][tid] = (tid == 0) ? 1.0f : 0.0f;
    const int L = lengths[b];
    const int* xrow = xs + (size_t)b * S;
    __syncthreads();
    int cur = 0;
    const int i0 = warp * 16;
    for (int t = 0; t < L; ++t) {
        const int a = __ldg(xrow + t);
        const float* Wa = W + (size_t)a * (NST * NST);
        const float* hsrc = hbuf[cur];
        float* hdst = hbuf[cur ^ 1];
        const float4 hA = ((const float4*)hsrc)[lane];
        const float4 hB = ((const float4*)hsrc)[32 + lane];
        #pragma unroll 4
        for (int r = 0; r < 16; ++r) {
            const int i = i0 + r;
            const float4* p = (const float4*)(Wa + (size_t)i * NST + lane * 4);
            const float4 wA = p[0];
            const float4 wB = p[32];
            float s = wA.x*hA.x + wA.y*hA.y + wA.z*hA.z + wA.w*hA.w
                    + wB.x*hB.x + wB.y*hB.y + wB.z*hB.z + wB.w*hB.w;
            s += __shfl_xor_sync(0xffffffffu, s, 16);
            s = warp_reduce16(s);
            if (lane == 0) hdst[i] = s;
        }
        __syncthreads();
        cur ^= 1;
    }
    const float* hf = hbuf[cur];
    if (warp < 2) {
        float s = 0.0f;
        #pragma unroll
        for (int i = lane; i < NST; i += 32) s += lin_w[warp * NST + i] * hf[i];
        s += __shfl_xor_sync(0xffffffffu, s, 16);
        s = warp_reduce16(s);
        if (lane == 0) out[b * 2 + warp] = s + lin_b[warp];
    }
}

extern "C" void kernel_launch(void* const* d_in, const int* in_sizes, int n_in,
                              void* d_out, int out_size)
{
    const int*   xs      = (const int*)d_in[0];
    const int*   lengths = (const int*)d_in[1];
    const float* W       = (const float*)d_in[2];
    const float* lin_w   = (const float*)d_in[3];
    const float* lin_b   = (const float*)d_in[4];
    float*       out     = (float*)d_out;

    const int B = in_sizes[1];
    const int S = in_sizes[0] / B;
    const int A = in_sizes[2] / (NST * NST);

    if (A >= 1 && A <= MAXA && B >= 1 && B <= MAXB) {
        const int total4 = in_sizes[2] / 4;
        pann_quant<<<2048, 256>>>(W, total4);
        const int sthreads = ((B + 31) / 32 * 32) < 32 ? 32 : ((B + 31) / 32 * 32);
        pann_sched<<<1, sthreads>>>(lengths, B);
        const int K = (B < KCTA) ? B : KCTA;
        pann_lpt24<<<K, TPB>>>(xs, lengths, lin_w, lin_b, out, S, B);
    } else {
        pann_chain_fp32<<<B, 512>>>(xs, lengths, W, lin_w, lin_b, out, S);
    }
}